// round 13
// baseline (speedup 1.0000x reference)
#include <cuda_runtime.h>
#include <cuda_fp16.h>
#include <cstdint>

#define NTOK     8192
#define DM       2048
#define DH       2048
#define NEXP     8
#define TOPK     2
#define TASSIGN  (NTOK * TOPK)
#define CAP      2560

#define BM 128
#define BK 32
#define KIT (2048 / BK)        // 64 k-slabs
#define NSTAGE 4
#define STAGE_BYTES 16384      // A 8KB + B 8KB

// ---------------- scratch (device globals) ----------------
__device__ int    g_counts[NEXP];
__device__ int    g_tok[NEXP * CAP];
__device__ int    g_slot[TASSIGN];
__device__ __half g_x16[(size_t)NTOK * DM];
__device__ __half g_w1t[(size_t)NEXP * DM * DH];
__device__ __half g_w2t[(size_t)NEXP * DH * DM];
__device__ __half g_w3t[(size_t)NEXP * DM * DH];
__device__ __half g_h  [(size_t)NEXP * CAP * DH];
__device__ float  g_y  [(size_t)NEXP * CAP * DM];

// ---------------- helpers ----------------
__device__ __forceinline__ uint32_t smem_u32(const void* p) {
    uint32_t a;
    asm("{ .reg .u64 t; cvta.to.shared.u64 t, %1; cvt.u32.u64 %0, t; }" : "=r"(a) : "l"(p));
    return a;
}
__device__ __forceinline__ uint32_t swz64(uint32_t o) { return o ^ ((o >> 3) & 0x30); }

__device__ __forceinline__ void cpasync16(uint32_t dst, const void* src) {
    asm volatile("cp.async.cg.shared.global [%0], [%1], 16;" :: "r"(dst), "l"(src) : "memory");
}
__device__ __forceinline__ void cp_commit() {
    asm volatile("cp.async.commit_group;" ::: "memory");
}
__device__ __forceinline__ void cp_wait1() {
    asm volatile("cp.async.wait_group 1;" ::: "memory");
}
__device__ __forceinline__ void cp_wait2() {
    asm volatile("cp.async.wait_group 2;" ::: "memory");
}

__device__ __forceinline__ void ldsm4(uint32_t& r0, uint32_t& r1, uint32_t& r2, uint32_t& r3,
                                      uint32_t addr) {
    asm volatile("ldmatrix.sync.aligned.m8n8.x4.shared.b16 {%0,%1,%2,%3}, [%4];"
                 : "=r"(r0), "=r"(r1), "=r"(r2), "=r"(r3) : "r"(addr));
}

__device__ __forceinline__ void mma16816(float* d, const uint32_t* a, const uint32_t* b) {
    asm volatile(
        "mma.sync.aligned.m16n8k16.row.col.f32.f16.f16.f32 "
        "{%0,%1,%2,%3}, {%4,%5,%6,%7}, {%8,%9}, {%0,%1,%2,%3};"
        : "+f"(d[0]), "+f"(d[1]), "+f"(d[2]), "+f"(d[3])
        : "r"(a[0]), "r"(a[1]), "r"(a[2]), "r"(a[3]), "r"(b[0]), "r"(b[1]));
}

// ---------------- routing ----------------
__global__ void route_kernel(const int* __restrict__ idx) {
    int w    = threadIdx.x >> 5;
    int lane = threadIdx.x & 31;
    if (w >= NEXP) return;
    int base = 0;
    for (int t0 = 0; t0 < TASSIGN; t0 += 32) {
        int t = t0 + lane;
        int e = idx[t];
        bool m = (e == w);
        unsigned mask = __ballot_sync(0xffffffffu, m);
        if (m) {
            int rank = base + __popc(mask & ((1u << lane) - 1u));
            int slot = -1;
            if (rank < CAP) {
                slot = w * CAP + rank;
                g_tok[slot] = t / TOPK;
            }
            g_slot[t] = slot;
        }
        base += __popc(mask);
    }
    if (lane == 0) g_counts[w] = base;
}

// ---------------- x convert: f32 -> fp16, vectorized ----------------
__global__ void xcvt_kernel(const float* __restrict__ x) {
    size_t i = ((size_t)blockIdx.x * blockDim.x + threadIdx.x) * 4;
    float4 v = *(const float4*)(x + i);
    __half2 h0 = __floats2half2_rn(v.x, v.y);
    __half2 h1 = __floats2half2_rn(v.z, v.w);
    uint2 pk;
    pk.x = *(uint32_t*)&h0;
    pk.y = *(uint32_t*)&h1;
    *(uint2*)(g_x16 + i) = pk;
}

// ---------------- weight transpose + fp16 convert (vectorized 64x64 tiles) ----------------
__global__ void wprep_kernel(const float* __restrict__ w1,
                             const float* __restrict__ w2,
                             const float* __restrict__ w3) {
    __shared__ float t[64][65];
    int z  = blockIdx.z;
    int e  = z & 7;
    int T  = z >> 3;                       // 0: w1, 1: w2, 2: w3
    const float* w = (T == 0) ? w1 : (T == 1) ? w2 : w3;
    __half* dst    = (T == 0) ? g_w1t : (T == 1) ? g_w2t : g_w3t;
    int d0 = blockIdx.y * 64, h0 = blockIdx.x * 64;
    int tid = threadIdx.x;
    int row = tid >> 4;            // 0..15
    int c4  = (tid & 15) * 4;      // 0..60

    const float* src = w + (size_t)e * DM * DH + (size_t)d0 * DH + h0;
#pragma unroll
    for (int p = 0; p < 4; p++) {
        float4 v = *(const float4*)(src + (size_t)(row + 16 * p) * DH + c4);
        t[row + 16 * p][c4 + 0] = v.x;
        t[row + 16 * p][c4 + 1] = v.y;
        t[row + 16 * p][c4 + 2] = v.z;
        t[row + 16 * p][c4 + 3] = v.w;
    }
    __syncthreads();

    __half* dbase = dst + (size_t)e * DM * DH + (size_t)h0 * DM + d0;
#pragma unroll
    for (int p = 0; p < 4; p++) {
        int oc = row + 16 * p;             // h-local
        float v0 = t[c4 + 0][oc];
        float v1 = t[c4 + 1][oc];
        float v2 = t[c4 + 2][oc];
        float v3 = t[c4 + 3][oc];
        __half2 h0p = __floats2half2_rn(v0, v1);
        __half2 h1p = __floats2half2_rn(v2, v3);
        uint2 pk;
        pk.x = *(uint32_t*)&h0p;
        pk.y = *(uint32_t*)&h1p;
        *(uint2*)(dbase + (size_t)oc * DM + c4) = pk;
    }
}

// ---------------- HMMA GEMM (fp16, BK=32, frag loads hoisted; fixed sync) ----------------
// Invariant: iteration kt's wait_group(1) drains slabs <= kt+1 per-thread; the
// barrier then publishes slab kt+1 CTA-wide, licensing iteration kt+1's
// pre-barrier LDSMs of stage (kt+1)%4. Pre-loop wait(2)+barrier publishes slab 0.
// MODE 1: fused x@w1 / x@w3 + SwiGLU -> g_h (CTA: 128 M x 64 N of each mat)
// MODE 2: h@w2 -> g_y                (CTA: 128 M x 128 N)
template <int MODE>
__global__ __launch_bounds__(256, 2) void hmma_gemm_kernel() {
    const int e = blockIdx.z;
    int cnt = g_counts[e];
    if (cnt > CAP) cnt = CAP;
    const int m0 = blockIdx.y * BM;
    if (m0 >= cnt) return;
    const int n0 = blockIdx.x * ((MODE == 1) ? 64 : 128);

    extern __shared__ __align__(1024) char smem[];
    uint32_t sb = smem_u32(smem);

    const int tid  = threadIdx.x;
    const int lane = tid & 31;
    const int wid  = tid >> 5;

    // ---- A cp.async: rows rA0 (0..63) and rA1 (64..127), 16B chunk (tid&3) ----
    const int rA0 = tid >> 2;
    const int rA1 = rA0 + 64;
    const int cA  = (tid & 3) * 8;      // halves
    const __half* paj[2];
    if (MODE == 1) {
        paj[0] = g_x16 + (size_t)g_tok[e * CAP + m0 + rA0] * DM + cA;
        paj[1] = g_x16 + (size_t)g_tok[e * CAP + m0 + rA1] * DM + cA;
    } else {
        paj[0] = g_h + ((size_t)e * CAP + m0 + rA0) * DH + cA;
        paj[1] = g_h + ((size_t)e * CAP + m0 + rA1) * DH + cA;
    }
    uint32_t soA[2];
    soA[0] = sb + swz64((uint32_t)(rA0 * 64 + (tid & 3) * 16));
    soA[1] = sb + swz64((uint32_t)(rA1 * 64 + (tid & 3) * 16));

    const __half* pbj[2];
    {
        int rB[2] = {rA0, rA1};
#pragma unroll
        for (int j = 0; j < 2; j++) {
            int rb = rB[j];
            if (MODE == 1) {
                if (rb < 64) pbj[j] = g_w1t + ((size_t)e * DH + n0 + rb) * DM + cA;
                else         pbj[j] = g_w3t + ((size_t)e * DH + n0 + rb - 64) * DM + cA;
            } else {
                pbj[j] = g_w2t + ((size_t)e * DM + n0 + rb) * DH + cA;
            }
        }
    }
    uint32_t soB[2];
    soB[0] = sb + 8192 + swz64((uint32_t)(rA0 * 64 + (tid & 3) * 16));
    soB[1] = sb + 8192 + swz64((uint32_t)(rA1 * 64 + (tid & 3) * 16));

    // ---- warp tiling ----
    int wm, wn, mat;
    if (MODE == 1) { wm = wid & 1; wn = (wid >> 1) & 1; mat = wid >> 2; }
    else           { wm = wid & 1; wn = wid >> 1;       mat = 0; }
    const int mbase = wm * 64;
    const int nbB   = (MODE == 1) ? (mat * 64 + wn * 32) : (wn * 32);

    const int lrow = lane & 15;
    const int lkb  = (lane & 16) ? 16 : 0;

    // ---- fully precomputed LDSM base addresses (chunk0 and chunk1 variants) ----
    uint32_t baseA[4], baseAx[4];
#pragma unroll
    for (int mi = 0; mi < 4; mi++) {
        uint32_t pre = (uint32_t)((mbase + mi * 16 + lrow) * 64 + lkb);
        baseA[mi]  = sb + swz64(pre);
        baseAx[mi] = sb + swz64(pre ^ 32u);
    }
    uint32_t baseB[2], baseBx[2];
#pragma unroll
    for (int g = 0; g < 2; g++) {
        uint32_t pre = (uint32_t)((nbB + g * 16 + lrow) * 64 + lkb);
        baseB[g]  = sb + 8192 + swz64(pre);
        baseBx[g] = sb + 8192 + swz64(pre ^ 32u);
    }

    float acc[4][4][4];
#pragma unroll
    for (int mi = 0; mi < 4; mi++)
#pragma unroll
        for (int ni = 0; ni < 4; ni++)
#pragma unroll
            for (int q = 0; q < 4; q++) acc[mi][ni][q] = 0.f;

    // ---- prologue: slabs 0..NSTAGE-2 ----
#pragma unroll
    for (int s = 0; s < NSTAGE - 1; s++) {
        uint32_t o = s * STAGE_BYTES;
        cpasync16(soA[0] + o, paj[0] + s * BK);
        cpasync16(soA[1] + o, paj[1] + s * BK);
        cpasync16(soB[0] + o, pbj[0] + s * BK);
        cpasync16(soB[1] + o, pbj[1] + s * BK);
        cp_commit();
    }
    paj[0] += (NSTAGE - 1) * BK;  paj[1] += (NSTAGE - 1) * BK;
    pbj[0] += (NSTAGE - 1) * BK;  pbj[1] += (NSTAGE - 1) * BK;

    // publish slab 0 CTA-wide before first pre-barrier loads
    cp_wait2();
    __syncthreads();

    // ---- main loop: blocks of NSTAGE slabs; stage offsets compile-time ----
    int kt = 0;
#pragma unroll 1
    for (int blk = 0; blk < KIT / NSTAGE; blk++) {
#pragma unroll
        for (int s = 0; s < NSTAGE; s++) {
            const uint32_t so = s * STAGE_BYTES;

            // drain slabs <= kt+1 (per-thread); slab kt already CTA-visible
            cp_wait1();

            // ---- hoisted fragment loads from stage s (before the barrier) ----
            uint32_t bf[2][4][2];
#pragma unroll
            for (int g = 0; g < 2; g++) {
                uint32_t q0, q1, q2, q3;
                ldsm4(q0, q1, q2, q3, baseB[g] + so);
                bf[0][g * 2 + 0][0] = q0; bf[0][g * 2 + 0][1] = q2;
                bf[0][g * 2 + 1][0] = q1; bf[0][g * 2 + 1][1] = q3;
                ldsm4(q0, q1, q2, q3, baseBx[g] + so);
                bf[1][g * 2 + 0][0] = q0; bf[1][g * 2 + 0][1] = q2;
                bf[1][g * 2 + 1][0] = q1; bf[1][g * 2 + 1][1] = q3;
            }
            uint32_t af0[4][4];
#pragma unroll
            for (int mi = 0; mi < 4; mi++)
                ldsm4(af0[mi][0], af0[mi][1], af0[mi][2], af0[mi][3],
                      baseA[mi] + so);

            // publishes slab kt+1; separates last iter's reads of stage
            // (s+NSTAGE-1)%NSTAGE from this iter's prefetch write to it
            __syncthreads();

            // prefetch slab kt+NSTAGE-1 into stage (s+NSTAGE-1)%NSTAGE
            if (kt + NSTAGE - 1 < KIT) {
                const uint32_t wo = ((s + NSTAGE - 1) & (NSTAGE - 1)) * STAGE_BYTES;
                cpasync16(soA[0] + wo, paj[0]);
                cpasync16(soA[1] + wo, paj[1]);
                cpasync16(soB[0] + wo, pbj[0]);
                cpasync16(soB[1] + wo, pbj[1]);
            }
            cp_commit();
            paj[0] += BK; paj[1] += BK; pbj[0] += BK; pbj[1] += BK;

            // ---- chunk 1 A loads overlap chunk 0 MMAs ----
            uint32_t af1[4][4];
#pragma unroll
            for (int mi = 0; mi < 4; mi++)
                ldsm4(af1[mi][0], af1[mi][1], af1[mi][2], af1[mi][3],
                      baseAx[mi] + so);
#pragma unroll
            for (int mi = 0; mi < 4; mi++)
#pragma unroll
                for (int ni = 0; ni < 4; ni++)
                    mma16816(acc[mi][ni], af0[mi], bf[0][ni]);
#pragma unroll
            for (int mi = 0; mi < 4; mi++)
#pragma unroll
                for (int ni = 0; ni < 4; ni++)
                    mma16816(acc[mi][ni], af1[mi], bf[1][ni]);
            kt++;
        }
    }

    // ---- epilogue ----
    __syncthreads();
    if (MODE == 1) {
        float* fb = (float*)smem;   // 128 x 64 fp32 = 32KB scratch (reuse stages)
        if (mat == 1) {
#pragma unroll
            for (int mi = 0; mi < 4; mi++)
#pragma unroll
                for (int ni = 0; ni < 4; ni++) {
                    int ml = mbase + mi * 16 + (lane >> 2);
                    int nl = wn * 32 + ni * 8 + 2 * (lane & 3);
                    fb[ml * 64 + nl]           = acc[mi][ni][0];
                    fb[ml * 64 + nl + 1]       = acc[mi][ni][1];
                    fb[(ml + 8) * 64 + nl]     = acc[mi][ni][2];
                    fb[(ml + 8) * 64 + nl + 1] = acc[mi][ni][3];
                }
        }
        __syncthreads();
        if (mat == 0) {
#pragma unroll
            for (int mi = 0; mi < 4; mi++)
#pragma unroll
                for (int ni = 0; ni < 4; ni++) {
                    int ml = mbase + mi * 16 + (lane >> 2);
                    int nl = wn * 32 + ni * 8 + 2 * (lane & 3);
#pragma unroll
                    for (int hrow = 0; hrow < 2; hrow++) {
                        int mloc = ml + hrow * 8;
                        int row  = m0 + mloc;
                        if (row >= cnt) continue;
                        float a10 = acc[mi][ni][2 * hrow + 0];
                        float a11 = acc[mi][ni][2 * hrow + 1];
                        float a30 = fb[mloc * 64 + nl];
                        float a31 = fb[mloc * 64 + nl + 1];
                        float h0 = (a10 / (1.f + __expf(-a10))) * a30;
                        float h1 = (a11 / (1.f + __expf(-a11))) * a31;
                        __half2 hp = __floats2half2_rn(h0, h1);
                        size_t o = ((size_t)e * CAP + row) * DH + n0 + nl;
                        *(__half2*)(g_h + o) = hp;
                    }
                }
        }
    } else {
#pragma unroll
        for (int mi = 0; mi < 4; mi++)
#pragma unroll
            for (int ni = 0; ni < 4; ni++) {
                int ml = mbase + mi * 16 + (lane >> 2);
                int nl = nbB + ni * 8 + 2 * (lane & 3);
#pragma unroll
                for (int hrow = 0; hrow < 2; hrow++) {
                    int row = m0 + ml + hrow * 8;
                    if (row >= cnt) continue;
                    float2 v = make_float2(acc[mi][ni][2 * hrow], acc[mi][ni][2 * hrow + 1]);
                    *(float2*)(g_y + ((size_t)e * CAP + row) * DM + n0 + nl) = v;
                }
            }
    }
}

// ---------------- combine ----------------
__global__ void combine_kernel(const float* __restrict__ ew, float* __restrict__ out) {
    int i = blockIdx.x * blockDim.x + threadIdx.x;
    int n = i / (DM / 4);
    int c = (i % (DM / 4)) * 4;
    float4 r = make_float4(0.f, 0.f, 0.f, 0.f);
#pragma unroll
    for (int k = 0; k < TOPK; k++) {
        int slot = g_slot[n * TOPK + k];
        if (slot >= 0) {
            float w = ew[n * TOPK + k];
            float4 v = *(const float4*)(g_y + (size_t)slot * DM + c);
            r.x = fmaf(w, v.x, r.x);
            r.y = fmaf(w, v.y, r.y);
            r.z = fmaf(w, v.z, r.z);
            r.w = fmaf(w, v.w, r.w);
        }
    }
    *(float4*)(out + (size_t)n * DM + c) = r;
}

__global__ void counts_kernel(float* __restrict__ out_tail) {
    if (threadIdx.x < NEXP) out_tail[threadIdx.x] = (float)g_counts[threadIdx.x];
}

// ---------------- launch ----------------
extern "C" void kernel_launch(void* const* d_in, const int* in_sizes, int n_in,
                              void* d_out, int out_size) {
    const float* x  = (const float*)d_in[0];
    const float* ew = (const float*)d_in[1];
    const int*   ix = (const int*)  d_in[2];
    const float* w1 = (const float*)d_in[3];
    const float* w2 = (const float*)d_in[4];
    const float* w3 = (const float*)d_in[5];
    float* out = (float*)d_out;

    const int SMEM = NSTAGE * STAGE_BYTES;   // 65536
    cudaFuncSetAttribute(hmma_gemm_kernel<1>, cudaFuncAttributeMaxDynamicSharedMemorySize, SMEM);
    cudaFuncSetAttribute(hmma_gemm_kernel<2>, cudaFuncAttributeMaxDynamicSharedMemorySize, SMEM);

    route_kernel<<<1, 256>>>(ix);
    xcvt_kernel<<<(NTOK * DM / 4) / 256, 256>>>(x);

    dim3 wg(DH / 64, DM / 64, 3 * NEXP);     // 32 x 32 x 24
    wprep_kernel<<<wg, 256>>>(w1, w2, w3);

    dim3 g1(DH / 64, CAP / BM, NEXP);    // 32 x 20 x 8
    hmma_gemm_kernel<1><<<g1, 256, SMEM>>>();

    dim3 g2(DM / 128, CAP / BM, NEXP);   // 16 x 20 x 8
    hmma_gemm_kernel<2><<<g2, 256, SMEM>>>();

    combine_kernel<<<(NTOK * (DM / 4)) / 256, 256>>>(ew, out);

    if (out_size >= NTOK * DM + NEXP)
        counts_kernel<<<1, 32>>>(out + (size_t)NTOK * DM);
}

// round 14
// speedup vs baseline: 1.0625x; 1.0625x over previous
#include <cuda_runtime.h>
#include <cuda_fp16.h>
#include <cstdint>

#define NTOK     8192
#define DM       2048
#define DH       2048
#define NEXP     8
#define TOPK     2
#define TASSIGN  (NTOK * TOPK)
#define CAP      2560

#define BM 128
#define BK 32
#define KIT (2048 / BK)        // 64 k-slabs
#define NSTAGE 4
#define STAGE_BYTES 16384      // A 8KB + B 8KB

// ---------------- scratch (device globals) ----------------
__device__ int    g_counts[NEXP];
__device__ int    g_tok[NEXP * CAP];
__device__ int    g_slot[TASSIGN];
__device__ __half g_x16[(size_t)NTOK * DM];
__device__ __half g_w1t[(size_t)NEXP * DM * DH];
__device__ __half g_w2t[(size_t)NEXP * DH * DM];
__device__ __half g_w3t[(size_t)NEXP * DM * DH];
__device__ __half g_h  [(size_t)NEXP * CAP * DH];
__device__ float  g_y  [(size_t)NEXP * CAP * DM];

// ---------------- helpers ----------------
__device__ __forceinline__ uint32_t smem_u32(const void* p) {
    uint32_t a;
    asm("{ .reg .u64 t; cvta.to.shared.u64 t, %1; cvt.u32.u64 %0, t; }" : "=r"(a) : "l"(p));
    return a;
}
__device__ __forceinline__ uint32_t swz64(uint32_t o) { return o ^ ((o >> 3) & 0x30); }

__device__ __forceinline__ void cpasync16(uint32_t dst, const void* src) {
    asm volatile("cp.async.cg.shared.global [%0], [%1], 16;" :: "r"(dst), "l"(src) : "memory");
}
__device__ __forceinline__ void cp_commit() {
    asm volatile("cp.async.commit_group;" ::: "memory");
}
__device__ __forceinline__ void cp_wait2() {
    asm volatile("cp.async.wait_group 2;" ::: "memory");
}

__device__ __forceinline__ void ldsm4(uint32_t& r0, uint32_t& r1, uint32_t& r2, uint32_t& r3,
                                      uint32_t addr) {
    asm volatile("ldmatrix.sync.aligned.m8n8.x4.shared.b16 {%0,%1,%2,%3}, [%4];"
                 : "=r"(r0), "=r"(r1), "=r"(r2), "=r"(r3) : "r"(addr));
}

__device__ __forceinline__ void mma16816(float* d, const uint32_t* a, const uint32_t* b) {
    asm volatile(
        "mma.sync.aligned.m16n8k16.row.col.f32.f16.f16.f32 "
        "{%0,%1,%2,%3}, {%4,%5,%6,%7}, {%8,%9}, {%0,%1,%2,%3};"
        : "+f"(d[0]), "+f"(d[1]), "+f"(d[2]), "+f"(d[3])
        : "r"(a[0]), "r"(a[1]), "r"(a[2]), "r"(a[3]), "r"(b[0]), "r"(b[1]));
}

// ---------------- routing ----------------
__global__ void route_kernel(const int* __restrict__ idx) {
    int w    = threadIdx.x >> 5;
    int lane = threadIdx.x & 31;
    if (w >= NEXP) return;
    int base = 0;
    for (int t0 = 0; t0 < TASSIGN; t0 += 32) {
        int t = t0 + lane;
        int e = idx[t];
        bool m = (e == w);
        unsigned mask = __ballot_sync(0xffffffffu, m);
        if (m) {
            int rank = base + __popc(mask & ((1u << lane) - 1u));
            int slot = -1;
            if (rank < CAP) {
                slot = w * CAP + rank;
                g_tok[slot] = t / TOPK;
            }
            g_slot[t] = slot;
        }
        base += __popc(mask);
    }
    if (lane == 0) g_counts[w] = base;
}

// ---------------- x convert: f32 -> fp16, vectorized ----------------
__global__ void xcvt_kernel(const float* __restrict__ x) {
    size_t i = ((size_t)blockIdx.x * blockDim.x + threadIdx.x) * 4;
    float4 v = *(const float4*)(x + i);
    __half2 h0 = __floats2half2_rn(v.x, v.y);
    __half2 h1 = __floats2half2_rn(v.z, v.w);
    uint2 pk;
    pk.x = *(uint32_t*)&h0;
    pk.y = *(uint32_t*)&h1;
    *(uint2*)(g_x16 + i) = pk;
}

// ---------------- weight transpose + fp16 convert (vectorized 64x64 tiles) ----------------
__global__ void wprep_kernel(const float* __restrict__ w1,
                             const float* __restrict__ w2,
                             const float* __restrict__ w3) {
    __shared__ float t[64][65];
    int z  = blockIdx.z;
    int e  = z & 7;
    int T  = z >> 3;                       // 0: w1, 1: w2, 2: w3
    const float* w = (T == 0) ? w1 : (T == 1) ? w2 : w3;
    __half* dst    = (T == 0) ? g_w1t : (T == 1) ? g_w2t : g_w3t;
    int d0 = blockIdx.y * 64, h0 = blockIdx.x * 64;
    int tid = threadIdx.x;
    int row = tid >> 4;            // 0..15
    int c4  = (tid & 15) * 4;      // 0..60

    const float* src = w + (size_t)e * DM * DH + (size_t)d0 * DH + h0;
#pragma unroll
    for (int p = 0; p < 4; p++) {
        float4 v = *(const float4*)(src + (size_t)(row + 16 * p) * DH + c4);
        t[row + 16 * p][c4 + 0] = v.x;
        t[row + 16 * p][c4 + 1] = v.y;
        t[row + 16 * p][c4 + 2] = v.z;
        t[row + 16 * p][c4 + 3] = v.w;
    }
    __syncthreads();

    __half* dbase = dst + (size_t)e * DM * DH + (size_t)h0 * DM + d0;
#pragma unroll
    for (int p = 0; p < 4; p++) {
        int oc = row + 16 * p;             // h-local
        float v0 = t[c4 + 0][oc];
        float v1 = t[c4 + 1][oc];
        float v2 = t[c4 + 2][oc];
        float v3 = t[c4 + 3][oc];
        __half2 h0p = __floats2half2_rn(v0, v1);
        __half2 h1p = __floats2half2_rn(v2, v3);
        uint2 pk;
        pk.x = *(uint32_t*)&h0p;
        pk.y = *(uint32_t*)&h1p;
        *(uint2*)(dbase + (size_t)oc * DM + c4) = pk;
    }
}

// ---------------- HMMA GEMM (plain fp16, BK=32, zero per-slab addr ALU) ----------------
// Stage: [A 8KB][B 8KB]; both tiles 128 rows x 64B (32 halves), SW64 swizzle.
// MODE 1: fused x@w1 / x@w3 + SwiGLU -> g_h (CTA: 128 M x 64 N of each mat)
// MODE 2: h@w2 -> g_y                (CTA: 128 M x 128 N)
template <int MODE>
__global__ __launch_bounds__(256, 2) void hmma_gemm_kernel() {
    const int e = blockIdx.z;
    int cnt = g_counts[e];
    if (cnt > CAP) cnt = CAP;
    const int m0 = blockIdx.y * BM;
    if (m0 >= cnt) return;
    const int n0 = blockIdx.x * ((MODE == 1) ? 64 : 128);

    extern __shared__ __align__(1024) char smem[];
    uint32_t sb = smem_u32(smem);

    const int tid  = threadIdx.x;
    const int lane = tid & 31;
    const int wid  = tid >> 5;

    // ---- A cp.async: rows rA0 (0..63) and rA1 (64..127), 16B chunk (tid&3) ----
    const int rA0 = tid >> 2;
    const int rA1 = rA0 + 64;
    const int cA  = (tid & 3) * 8;      // halves
    const __half* paj[2];
    if (MODE == 1) {
        paj[0] = g_x16 + (size_t)g_tok[e * CAP + m0 + rA0] * DM + cA;
        paj[1] = g_x16 + (size_t)g_tok[e * CAP + m0 + rA1] * DM + cA;
    } else {
        paj[0] = g_h + ((size_t)e * CAP + m0 + rA0) * DH + cA;
        paj[1] = g_h + ((size_t)e * CAP + m0 + rA1) * DH + cA;
    }
    uint32_t soA[2];
    soA[0] = sb + swz64((uint32_t)(rA0 * 64 + (tid & 3) * 16));
    soA[1] = sb + swz64((uint32_t)(rA1 * 64 + (tid & 3) * 16));

    const __half* pbj[2];
    {
        int rB[2] = {rA0, rA1};
#pragma unroll
        for (int j = 0; j < 2; j++) {
            int rb = rB[j];
            if (MODE == 1) {
                if (rb < 64) pbj[j] = g_w1t + ((size_t)e * DH + n0 + rb) * DM + cA;
                else         pbj[j] = g_w3t + ((size_t)e * DH + n0 + rb - 64) * DM + cA;
            } else {
                pbj[j] = g_w2t + ((size_t)e * DM + n0 + rb) * DH + cA;
            }
        }
    }
    uint32_t soB[2];
    soB[0] = sb + 8192 + swz64((uint32_t)(rA0 * 64 + (tid & 3) * 16));
    soB[1] = sb + 8192 + swz64((uint32_t)(rA1 * 64 + (tid & 3) * 16));

    // ---- warp tiling ----
    int wm, wn, mat;
    if (MODE == 1) { wm = wid & 1; wn = (wid >> 1) & 1; mat = wid >> 2; }
    else           { wm = wid & 1; wn = wid >> 1;       mat = 0; }
    const int mbase = wm * 64;
    const int nbB   = (MODE == 1) ? (mat * 64 + wn * 32) : (wn * 32);

    const int lrow = lane & 15;
    const int lkb  = (lane & 16) ? 16 : 0;

    // ---- fully precomputed LDSM base addresses (chunk0 and chunk1 variants) ----
    uint32_t baseA[4], baseAx[4];
#pragma unroll
    for (int mi = 0; mi < 4; mi++) {
        uint32_t pre = (uint32_t)((mbase + mi * 16 + lrow) * 64 + lkb);
        baseA[mi]  = sb + swz64(pre);
        baseAx[mi] = sb + swz64(pre ^ 32u);
    }
    uint32_t baseB[2], baseBx[2];
#pragma unroll
    for (int g = 0; g < 2; g++) {
        uint32_t pre = (uint32_t)((nbB + g * 16 + lrow) * 64 + lkb);
        baseB[g]  = sb + 8192 + swz64(pre);
        baseBx[g] = sb + 8192 + swz64(pre ^ 32u);
    }

    float acc[4][4][4];
#pragma unroll
    for (int mi = 0; mi < 4; mi++)
#pragma unroll
        for (int ni = 0; ni < 4; ni++)
#pragma unroll
            for (int q = 0; q < 4; q++) acc[mi][ni][q] = 0.f;

    // ---- prologue: slabs 0..NSTAGE-2 ----
#pragma unroll
    for (int s = 0; s < NSTAGE - 1; s++) {
        uint32_t o = s * STAGE_BYTES;
        cpasync16(soA[0] + o, paj[0] + s * BK);
        cpasync16(soA[1] + o, paj[1] + s * BK);
        cpasync16(soB[0] + o, pbj[0] + s * BK);
        cpasync16(soB[1] + o, pbj[1] + s * BK);
        cp_commit();
    }
    paj[0] += (NSTAGE - 1) * BK;  paj[1] += (NSTAGE - 1) * BK;
    pbj[0] += (NSTAGE - 1) * BK;  pbj[1] += (NSTAGE - 1) * BK;

    // ---- main loop: blocks of NSTAGE slabs; stage offsets compile-time ----
    int kt = 0;
#pragma unroll 1
    for (int blk = 0; blk < KIT / NSTAGE; blk++) {
#pragma unroll
        for (int s = 0; s < NSTAGE; s++) {
            cp_wait2();
            __syncthreads();

            // prefetch slab kt+NSTAGE-1 into stage (s+NSTAGE-1)%NSTAGE
            if (kt + NSTAGE - 1 < KIT) {
                const uint32_t wo = ((s + NSTAGE - 1) & (NSTAGE - 1)) * STAGE_BYTES;
                cpasync16(soA[0] + wo, paj[0]);
                cpasync16(soA[1] + wo, paj[1]);
                cpasync16(soB[0] + wo, pbj[0]);
                cpasync16(soB[1] + wo, pbj[1]);
            }
            cp_commit();
            paj[0] += BK; paj[1] += BK; pbj[0] += BK; pbj[1] += BK;

            const uint32_t so = s * STAGE_BYTES;

            // B fragments for both k-chunks (addresses: base + imm, zero ALU)
            uint32_t bf[2][4][2];
#pragma unroll
            for (int g = 0; g < 2; g++) {
                uint32_t q0, q1, q2, q3;
                ldsm4(q0, q1, q2, q3, baseB[g] + so);
                bf[0][g * 2 + 0][0] = q0; bf[0][g * 2 + 0][1] = q2;
                bf[0][g * 2 + 1][0] = q1; bf[0][g * 2 + 1][1] = q3;
                ldsm4(q0, q1, q2, q3, baseBx[g] + so);
                bf[1][g * 2 + 0][0] = q0; bf[1][g * 2 + 0][1] = q2;
                bf[1][g * 2 + 1][0] = q1; bf[1][g * 2 + 1][1] = q3;
            }

            // per k-chunk: A fragments then 16 MMAs
#pragma unroll
            for (int c = 0; c < 2; c++) {
                uint32_t af[4][4];
#pragma unroll
                for (int mi = 0; mi < 4; mi++)
                    ldsm4(af[mi][0], af[mi][1], af[mi][2], af[mi][3],
                          (c ? baseAx[mi] : baseA[mi]) + so);
#pragma unroll
                for (int mi = 0; mi < 4; mi++)
#pragma unroll
                    for (int ni = 0; ni < 4; ni++)
                        mma16816(acc[mi][ni], af[mi], bf[c][ni]);
            }
            kt++;
        }
    }

    // ---- epilogue ----
    __syncthreads();
    if (MODE == 1) {
        float* fb = (float*)smem;   // 128 x 64 fp32 = 32KB scratch (reuse stages)
        if (mat == 1) {
#pragma unroll
            for (int mi = 0; mi < 4; mi++)
#pragma unroll
                for (int ni = 0; ni < 4; ni++) {
                    int ml = mbase + mi * 16 + (lane >> 2);
                    int nl = wn * 32 + ni * 8 + 2 * (lane & 3);
                    fb[ml * 64 + nl]           = acc[mi][ni][0];
                    fb[ml * 64 + nl + 1]       = acc[mi][ni][1];
                    fb[(ml + 8) * 64 + nl]     = acc[mi][ni][2];
                    fb[(ml + 8) * 64 + nl + 1] = acc[mi][ni][3];
                }
        }
        __syncthreads();
        if (mat == 0) {
#pragma unroll
            for (int mi = 0; mi < 4; mi++)
#pragma unroll
                for (int ni = 0; ni < 4; ni++) {
                    int ml = mbase + mi * 16 + (lane >> 2);
                    int nl = wn * 32 + ni * 8 + 2 * (lane & 3);
#pragma unroll
                    for (int hrow = 0; hrow < 2; hrow++) {
                        int mloc = ml + hrow * 8;
                        int row  = m0 + mloc;
                        if (row >= cnt) continue;
                        float a10 = acc[mi][ni][2 * hrow + 0];
                        float a11 = acc[mi][ni][2 * hrow + 1];
                        float a30 = fb[mloc * 64 + nl];
                        float a31 = fb[mloc * 64 + nl + 1];
                        float h0 = (a10 / (1.f + __expf(-a10))) * a30;
                        float h1 = (a11 / (1.f + __expf(-a11))) * a31;
                        __half2 hp = __floats2half2_rn(h0, h1);
                        size_t o = ((size_t)e * CAP + row) * DH + n0 + nl;
                        *(__half2*)(g_h + o) = hp;
                    }
                }
        }
    } else {
#pragma unroll
        for (int mi = 0; mi < 4; mi++)
#pragma unroll
            for (int ni = 0; ni < 4; ni++) {
                int ml = mbase + mi * 16 + (lane >> 2);
                int nl = nbB + ni * 8 + 2 * (lane & 3);
#pragma unroll
                for (int hrow = 0; hrow < 2; hrow++) {
                    int row = m0 + ml + hrow * 8;
                    if (row >= cnt) continue;
                    float2 v = make_float2(acc[mi][ni][2 * hrow], acc[mi][ni][2 * hrow + 1]);
                    *(float2*)(g_y + ((size_t)e * CAP + row) * DM + n0 + nl) = v;
                }
            }
    }
}

// ---------------- combine (+ counts tail fused) ----------------
__global__ void combine_kernel(const float* __restrict__ ew, float* __restrict__ out,
                               int write_counts) {
    int i = blockIdx.x * blockDim.x + threadIdx.x;   // 2 float4 per thread
    int n = i / (DM / 8);
    int c = (i % (DM / 8)) * 8;
    float4 r0 = make_float4(0.f, 0.f, 0.f, 0.f);
    float4 r1 = make_float4(0.f, 0.f, 0.f, 0.f);
#pragma unroll
    for (int k = 0; k < TOPK; k++) {
        int slot = g_slot[n * TOPK + k];
        if (slot >= 0) {
            float w = ew[n * TOPK + k];
            const float* yp = g_y + (size_t)slot * DM + c;
            float4 v0 = *(const float4*)(yp);
            float4 v1 = *(const float4*)(yp + 4);
            r0.x = fmaf(w, v0.x, r0.x); r0.y = fmaf(w, v0.y, r0.y);
            r0.z = fmaf(w, v0.z, r0.z); r0.w = fmaf(w, v0.w, r0.w);
            r1.x = fmaf(w, v1.x, r1.x); r1.y = fmaf(w, v1.y, r1.y);
            r1.z = fmaf(w, v1.z, r1.z); r1.w = fmaf(w, v1.w, r1.w);
        }
    }
    float* op = out + (size_t)n * DM + c;
    *(float4*)(op)     = r0;
    *(float4*)(op + 4) = r1;

    if (write_counts && blockIdx.x == 0 && threadIdx.x < NEXP)
        out[(size_t)NTOK * DM + threadIdx.x] = (float)g_counts[threadIdx.x];
}

// ---------------- launch ----------------
extern "C" void kernel_launch(void* const* d_in, const int* in_sizes, int n_in,
                              void* d_out, int out_size) {
    const float* x  = (const float*)d_in[0];
    const float* ew = (const float*)d_in[1];
    const int*   ix = (const int*)  d_in[2];
    const float* w1 = (const float*)d_in[3];
    const float* w2 = (const float*)d_in[4];
    const float* w3 = (const float*)d_in[5];
    float* out = (float*)d_out;

    const int SMEM = NSTAGE * STAGE_BYTES;   // 65536
    cudaFuncSetAttribute(hmma_gemm_kernel<1>, cudaFuncAttributeMaxDynamicSharedMemorySize, SMEM);
    cudaFuncSetAttribute(hmma_gemm_kernel<2>, cudaFuncAttributeMaxDynamicSharedMemorySize, SMEM);

    route_kernel<<<1, 256>>>(ix);
    xcvt_kernel<<<(NTOK * DM / 4) / 256, 256>>>(x);

    dim3 wg(DH / 64, DM / 64, 3 * NEXP);     // 32 x 32 x 24
    wprep_kernel<<<wg, 256>>>(w1, w2, w3);

    dim3 g1(DH / 64, CAP / BM, NEXP);    // 32 x 20 x 8
    hmma_gemm_kernel<1><<<g1, 256, SMEM>>>();

    dim3 g2(DM / 128, CAP / BM, NEXP);   // 16 x 20 x 8
    hmma_gemm_kernel<2><<<g2, 256, SMEM>>>();

    int wc = (out_size >= NTOK * DM + NEXP) ? 1 : 0;
    combine_kernel<<<(NTOK * (DM / 8)) / 256, 256>>>(ew, out, wc);
}

// round 15
// speedup vs baseline: 1.2982x; 1.2219x over previous
#include <cuda_runtime.h>
#include <cuda_fp16.h>
#include <cstdint>

#define NTOK     8192
#define DM       2048
#define DH       2048
#define NEXP     8
#define TOPK     2
#define TASSIGN  (NTOK * TOPK)
#define CAP      2560

#define BM 128
#define BK 32
#define KIT (2048 / BK)        // 64 k-slabs
#define NSTAGE 4
#define STAGE_BYTES 16384      // A 8KB + B 8KB

// ---------------- scratch (device globals) ----------------
__device__ int    g_counts[NEXP];
__device__ int    g_tok[NEXP * CAP];
__device__ int    g_slot[TASSIGN];
__device__ __half g_x16[(size_t)NTOK * DM];
__device__ __half g_w1f[(size_t)NEXP * DM * DH];   // fp16, ORIGINAL [d][h] layout
__device__ __half g_w2f[(size_t)NEXP * DH * DM];   // fp16, ORIGINAL [h][d] layout
__device__ __half g_w3f[(size_t)NEXP * DM * DH];
__device__ __half g_h  [(size_t)NEXP * CAP * DH];
__device__ float  g_y  [(size_t)NEXP * CAP * DM];

// ---------------- helpers ----------------
__device__ __forceinline__ uint32_t smem_u32(const void* p) {
    uint32_t a;
    asm("{ .reg .u64 t; cvta.to.shared.u64 t, %1; cvt.u32.u64 %0, t; }" : "=r"(a) : "l"(p));
    return a;
}
__device__ __forceinline__ uint32_t swz64(uint32_t o) { return o ^ ((o >> 3) & 0x30); }

__device__ __forceinline__ void cpasync16(uint32_t dst, const void* src) {
    asm volatile("cp.async.cg.shared.global [%0], [%1], 16;" :: "r"(dst), "l"(src) : "memory");
}
__device__ __forceinline__ void cp_commit() {
    asm volatile("cp.async.commit_group;" ::: "memory");
}
__device__ __forceinline__ void cp_wait2() {
    asm volatile("cp.async.wait_group 2;" ::: "memory");
}

__device__ __forceinline__ void ldsm4(uint32_t& r0, uint32_t& r1, uint32_t& r2, uint32_t& r3,
                                      uint32_t addr) {
    asm volatile("ldmatrix.sync.aligned.m8n8.x4.shared.b16 {%0,%1,%2,%3}, [%4];"
                 : "=r"(r0), "=r"(r1), "=r"(r2), "=r"(r3) : "r"(addr));
}
__device__ __forceinline__ void ldsm4t(uint32_t& r0, uint32_t& r1, uint32_t& r2, uint32_t& r3,
                                       uint32_t addr) {
    asm volatile("ldmatrix.sync.aligned.m8n8.x4.trans.shared.b16 {%0,%1,%2,%3}, [%4];"
                 : "=r"(r0), "=r"(r1), "=r"(r2), "=r"(r3) : "r"(addr));
}

__device__ __forceinline__ void mma16816(float* d, const uint32_t* a, const uint32_t* b) {
    asm volatile(
        "mma.sync.aligned.m16n8k16.row.col.f32.f16.f16.f32 "
        "{%0,%1,%2,%3}, {%4,%5,%6,%7}, {%8,%9}, {%0,%1,%2,%3};"
        : "+f"(d[0]), "+f"(d[1]), "+f"(d[2]), "+f"(d[3])
        : "r"(a[0]), "r"(a[1]), "r"(a[2]), "r"(a[3]), "r"(b[0]), "r"(b[1]));
}

// ---------------- routing: parallel, 1 block per expert, stable scan ----------------
__global__ void route_kernel(const int* __restrict__ idx) {
    const int e    = blockIdx.x;
    const int tid  = threadIdx.x;
    const int wid  = tid >> 5;
    const int lane = tid & 31;
    __shared__ int wcnt[8];

    int base = 0;
    for (int t0 = 0; t0 < TASSIGN; t0 += 256) {
        int t = t0 + tid;
        bool m = (idx[t] == e);
        unsigned mask = __ballot_sync(0xffffffffu, m);
        if (lane == 0) wcnt[wid] = __popc(mask);
        __syncthreads();
        int pre = 0, tot = 0;
#pragma unroll
        for (int w = 0; w < 8; w++) {
            int c = wcnt[w];
            if (w < wid) pre += c;
            tot += c;
        }
        if (m) {
            int rank = base + pre + __popc(mask & ((1u << lane) - 1u));
            int slot = -1;
            if (rank < CAP) {
                slot = e * CAP + rank;
                g_tok[slot] = t / TOPK;
            }
            g_slot[t] = slot;
        }
        base += tot;
        __syncthreads();
    }
    if (tid == 0) g_counts[e] = base;
}

// ---------------- x convert: f32 -> fp16, vectorized ----------------
__global__ void xcvt_kernel(const float* __restrict__ x) {
    size_t i = ((size_t)blockIdx.x * blockDim.x + threadIdx.x) * 4;
    float4 v = *(const float4*)(x + i);
    __half2 h0 = __floats2half2_rn(v.x, v.y);
    __half2 h1 = __floats2half2_rn(v.z, v.w);
    uint2 pk;
    pk.x = *(uint32_t*)&h0;
    pk.y = *(uint32_t*)&h1;
    *(uint2*)(g_x16 + i) = pk;
}

// ---------------- weight convert (streaming, NO transpose) ----------------
__global__ void wcvt_kernel(const float* __restrict__ w1,
                            const float* __restrict__ w2,
                            const float* __restrict__ w3) {
    int T = blockIdx.z;
    const float* w = (T == 0) ? w1 : (T == 1) ? w2 : w3;
    __half* dst    = (T == 0) ? g_w1f : (T == 1) ? g_w2f : g_w3f;
    size_t i = ((size_t)blockIdx.y * DM * DH) +
               ((size_t)blockIdx.x * blockDim.x + threadIdx.x) * 4;
    float4 v = *(const float4*)(w + i);
    __half2 h0 = __floats2half2_rn(v.x, v.y);
    __half2 h1 = __floats2half2_rn(v.z, v.w);
    uint2 pk;
    pk.x = *(uint32_t*)&h0;
    pk.y = *(uint32_t*)&h1;
    *(uint2*)(dst + i) = pk;
}

// ---------------- HMMA GEMM (fp16, BK=32, B via ldmatrix.trans) ----------------
// Stage: [A 8KB: 128 m-rows x 64B SW64][B 8KB: 32 k-rows x 256B, row-xor swizzle].
// MODE 1: fused x@w1 / x@w3 + SwiGLU -> g_h; B row = [w1 64h | w3 64h].
// MODE 2: h@w2 -> g_y; B row = 128 n-halves of w2.
template <int MODE>
__global__ __launch_bounds__(256, 2) void hmma_gemm_kernel() {
    const int e = blockIdx.z;
    int cnt = g_counts[e];
    if (cnt > CAP) cnt = CAP;
    const int m0 = blockIdx.y * BM;
    if (m0 >= cnt) return;
    const int n0 = blockIdx.x * ((MODE == 1) ? 64 : 128);

    extern __shared__ __align__(1024) char smem[];
    uint32_t sb = smem_u32(smem);

    const int tid  = threadIdx.x;
    const int lane = tid & 31;
    const int wid  = tid >> 5;

    // ---- A cp.async: rows rA0 (0..63) and rA1 (64..127), 16B chunk (tid&3) ----
    const int rA0 = tid >> 2;
    const int rA1 = rA0 + 64;
    const int cA  = (tid & 3) * 8;      // halves
    const __half* paj[2];
    if (MODE == 1) {
        paj[0] = g_x16 + (size_t)g_tok[e * CAP + m0 + rA0] * DM + cA;
        paj[1] = g_x16 + (size_t)g_tok[e * CAP + m0 + rA1] * DM + cA;
    } else {
        paj[0] = g_h + ((size_t)e * CAP + m0 + rA0) * DH + cA;
        paj[1] = g_h + ((size_t)e * CAP + m0 + rA1) * DH + cA;
    }
    uint32_t soA[2];
    soA[0] = sb + swz64((uint32_t)(rA0 * 64 + (tid & 3) * 16));
    soA[1] = sb + swz64((uint32_t)(rA1 * 64 + (tid & 3) * 16));

    // ---- B cp.async: K-major rows. thread t -> k-rows (t>>4) and (t>>4)+16, n-chunk t&15 ----
    const int rB0 = tid >> 4;           // 0..15
    const int rB1 = rB0 + 16;           // 16..31
    const int cB  = tid & 15;           // 16B chunk within 256B row
    const __half* pbj[2];
    {
        int rBv[2] = {rB0, rB1};
#pragma unroll
        for (int j = 0; j < 2; j++) {
            int rb = rBv[j];
            if (MODE == 1) {
                if (cB < 8)
                    pbj[j] = g_w1f + ((size_t)e * DM + rb) * DH + n0 + cB * 8;
                else
                    pbj[j] = g_w3f + ((size_t)e * DM + rb) * DH + n0 + (cB - 8) * 8;
            } else {
                pbj[j] = g_w2f + ((size_t)e * DH + rb) * DM + n0 + cB * 8;
            }
        }
    }
    // dest: row*256 + cB*16, swizzle ^ ((row&7)<<4); rB0&7 == rB1&7
    const uint32_t swB = (uint32_t)((rB0 & 7) << 4);
    uint32_t soB[2];
    soB[0] = sb + 8192 + (((uint32_t)(rB0 * 256 + cB * 16)) ^ swB);
    soB[1] = sb + 8192 + (((uint32_t)(rB1 * 256 + cB * 16)) ^ swB);
    // per-slab B source advance = BK rows
    const size_t bstep = (size_t)BK * ((MODE == 1) ? DH : DM);

    // ---- warp tiling ----
    int wm, wn, mat;
    if (MODE == 1) { wm = wid & 1; wn = (wid >> 1) & 1; mat = wid >> 2; }
    else           { wm = wid & 1; wn = wid >> 1;       mat = 0; }
    const int mbase = wm * 64;
    const int nbB   = (MODE == 1) ? (mat * 64 + wn * 32) : (wn * 32);

    const int lrow = lane & 15;
    const int lkb  = (lane & 16) ? 16 : 0;

    // ---- A LDSM bases (unchanged) ----
    uint32_t baseA[4], baseAx[4];
#pragma unroll
    for (int mi = 0; mi < 4; mi++) {
        uint32_t pre = (uint32_t)((mbase + mi * 16 + lrow) * 64 + lkb);
        baseA[mi]  = sb + swz64(pre);
        baseAx[mi] = sb + swz64(pre ^ 32u);
    }
    // ---- B trans-LDSM bases: group g = lane>>3, lr = lane&7 ----
    // tile addr: k-row = c*16 + (g&1)*8 + lr ; n-col = nbB + j*16 + (g>>1)*8
    // swizzle XOR = (row&7)<<4 = lr<<4 (constant); chunk1 = +4096 bytes (16 rows)
    const int gB = lane >> 3;
    const int lr = lane & 7;
    uint32_t baseBT[2];
#pragma unroll
    for (int j = 0; j < 2; j++) {
        uint32_t o = (uint32_t)((((gB & 1) * 8 + lr) * 256) +
                                (nbB + j * 16 + (gB >> 1) * 8) * 2);
        baseBT[j] = sb + 8192 + (o ^ ((uint32_t)lr << 4));
    }

    float acc[4][4][4];
#pragma unroll
    for (int mi = 0; mi < 4; mi++)
#pragma unroll
        for (int ni = 0; ni < 4; ni++)
#pragma unroll
            for (int q = 0; q < 4; q++) acc[mi][ni][q] = 0.f;

    // ---- prologue: slabs 0..NSTAGE-2 ----
#pragma unroll
    for (int s = 0; s < NSTAGE - 1; s++) {
        uint32_t o = s * STAGE_BYTES;
        cpasync16(soA[0] + o, paj[0] + s * BK);
        cpasync16(soA[1] + o, paj[1] + s * BK);
        cpasync16(soB[0] + o, pbj[0] + s * bstep);
        cpasync16(soB[1] + o, pbj[1] + s * bstep);
        cp_commit();
    }
    paj[0] += (NSTAGE - 1) * BK;    paj[1] += (NSTAGE - 1) * BK;
    pbj[0] += (NSTAGE - 1) * bstep; pbj[1] += (NSTAGE - 1) * bstep;

    // ---- main loop: blocks of NSTAGE slabs; stage offsets compile-time ----
    int kt = 0;
#pragma unroll 1
    for (int blk = 0; blk < KIT / NSTAGE; blk++) {
#pragma unroll
        for (int s = 0; s < NSTAGE; s++) {
            cp_wait2();
            __syncthreads();

            if (kt + NSTAGE - 1 < KIT) {
                const uint32_t wo = ((s + NSTAGE - 1) & (NSTAGE - 1)) * STAGE_BYTES;
                cpasync16(soA[0] + wo, paj[0]);
                cpasync16(soA[1] + wo, paj[1]);
                cpasync16(soB[0] + wo, pbj[0]);
                cpasync16(soB[1] + wo, pbj[1]);
            }
            cp_commit();
            paj[0] += BK;    paj[1] += BK;
            pbj[0] += bstep; pbj[1] += bstep;

            const uint32_t so = s * STAGE_BYTES;

            // B fragments via trans ldsm: per k-chunk c, per j (16 n each):
            // q0 = b0(n..n+7), q1 = b1(n..n+7), q2 = b0(n+8..15), q3 = b1(n+8..15)
            uint32_t bf[2][4][2];
#pragma unroll
            for (int c = 0; c < 2; c++) {
#pragma unroll
                for (int j = 0; j < 2; j++) {
                    uint32_t q0, q1, q2, q3;
                    ldsm4t(q0, q1, q2, q3, baseBT[j] + so + (uint32_t)(c * 4096));
                    bf[c][j * 2 + 0][0] = q0; bf[c][j * 2 + 0][1] = q1;
                    bf[c][j * 2 + 1][0] = q2; bf[c][j * 2 + 1][1] = q3;
                }
            }

            // per k-chunk: A fragments then 16 MMAs
#pragma unroll
            for (int c = 0; c < 2; c++) {
                uint32_t af[4][4];
#pragma unroll
                for (int mi = 0; mi < 4; mi++)
                    ldsm4(af[mi][0], af[mi][1], af[mi][2], af[mi][3],
                          (c ? baseAx[mi] : baseA[mi]) + so);
#pragma unroll
                for (int mi = 0; mi < 4; mi++)
#pragma unroll
                    for (int ni = 0; ni < 4; ni++)
                        mma16816(acc[mi][ni], af[mi], bf[c][ni]);
            }
            kt++;
        }
    }

    // ---- epilogue ----
    __syncthreads();
    if (MODE == 1) {
        float* fb = (float*)smem;
        if (mat == 1) {
#pragma unroll
            for (int mi = 0; mi < 4; mi++)
#pragma unroll
                for (int ni = 0; ni < 4; ni++) {
                    int ml = mbase + mi * 16 + (lane >> 2);
                    int nl = wn * 32 + ni * 8 + 2 * (lane & 3);
                    fb[ml * 64 + nl]           = acc[mi][ni][0];
                    fb[ml * 64 + nl + 1]       = acc[mi][ni][1];
                    fb[(ml + 8) * 64 + nl]     = acc[mi][ni][2];
                    fb[(ml + 8) * 64 + nl + 1] = acc[mi][ni][3];
                }
        }
        __syncthreads();
        if (mat == 0) {
#pragma unroll
            for (int mi = 0; mi < 4; mi++)
#pragma unroll
                for (int ni = 0; ni < 4; ni++) {
                    int ml = mbase + mi * 16 + (lane >> 2);
                    int nl = wn * 32 + ni * 8 + 2 * (lane & 3);
#pragma unroll
                    for (int hrow = 0; hrow < 2; hrow++) {
                        int mloc = ml + hrow * 8;
                        int row  = m0 + mloc;
                        if (row >= cnt) continue;
                        float a10 = acc[mi][ni][2 * hrow + 0];
                        float a11 = acc[mi][ni][2 * hrow + 1];
                        float a30 = fb[mloc * 64 + nl];
                        float a31 = fb[mloc * 64 + nl + 1];
                        float h0 = (a10 / (1.f + __expf(-a10))) * a30;
                        float h1 = (a11 / (1.f + __expf(-a11))) * a31;
                        __half2 hp = __floats2half2_rn(h0, h1);
                        size_t o = ((size_t)e * CAP + row) * DH + n0 + nl;
                        *(__half2*)(g_h + o) = hp;
                    }
                }
        }
    } else {
#pragma unroll
        for (int mi = 0; mi < 4; mi++)
#pragma unroll
            for (int ni = 0; ni < 4; ni++) {
                int ml = mbase + mi * 16 + (lane >> 2);
                int nl = nbB + ni * 8 + 2 * (lane & 3);
#pragma unroll
                for (int hrow = 0; hrow < 2; hrow++) {
                    int row = m0 + ml + hrow * 8;
                    if (row >= cnt) continue;
                    float2 v = make_float2(acc[mi][ni][2 * hrow], acc[mi][ni][2 * hrow + 1]);
                    *(float2*)(g_y + ((size_t)e * CAP + row) * DM + n0 + nl) = v;
                }
            }
    }
}

// ---------------- combine (+ counts tail fused) ----------------
__global__ void combine_kernel(const float* __restrict__ ew, float* __restrict__ out,
                               int write_counts) {
    int i = blockIdx.x * blockDim.x + threadIdx.x;   // 2 float4 per thread
    int n = i / (DM / 8);
    int c = (i % (DM / 8)) * 8;
    float4 r0 = make_float4(0.f, 0.f, 0.f, 0.f);
    float4 r1 = make_float4(0.f, 0.f, 0.f, 0.f);
#pragma unroll
    for (int k = 0; k < TOPK; k++) {
        int slot = g_slot[n * TOPK + k];
        if (slot >= 0) {
            float w = ew[n * TOPK + k];
            const float* yp = g_y + (size_t)slot * DM + c;
            float4 v0 = *(const float4*)(yp);
            float4 v1 = *(const float4*)(yp + 4);
            r0.x = fmaf(w, v0.x, r0.x); r0.y = fmaf(w, v0.y, r0.y);
            r0.z = fmaf(w, v0.z, r0.z); r0.w = fmaf(w, v0.w, r0.w);
            r1.x = fmaf(w, v1.x, r1.x); r1.y = fmaf(w, v1.y, r1.y);
            r1.z = fmaf(w, v1.z, r1.z); r1.w = fmaf(w, v1.w, r1.w);
        }
    }
    float* op = out + (size_t)n * DM + c;
    *(float4*)(op)     = r0;
    *(float4*)(op + 4) = r1;

    if (write_counts && blockIdx.x == 0 && threadIdx.x < NEXP)
        out[(size_t)NTOK * DM + threadIdx.x] = (float)g_counts[threadIdx.x];
}

// ---------------- launch ----------------
extern "C" void kernel_launch(void* const* d_in, const int* in_sizes, int n_in,
                              void* d_out, int out_size) {
    const float* x  = (const float*)d_in[0];
    const float* ew = (const float*)d_in[1];
    const int*   ix = (const int*)  d_in[2];
    const float* w1 = (const float*)d_in[3];
    const float* w2 = (const float*)d_in[4];
    const float* w3 = (const float*)d_in[5];
    float* out = (float*)d_out;

    const int SMEM = NSTAGE * STAGE_BYTES;   // 65536
    cudaFuncSetAttribute(hmma_gemm_kernel<1>, cudaFuncAttributeMaxDynamicSharedMemorySize, SMEM);
    cudaFuncSetAttribute(hmma_gemm_kernel<2>, cudaFuncAttributeMaxDynamicSharedMemorySize, SMEM);

    route_kernel<<<NEXP, 256>>>(ix);
    xcvt_kernel<<<(NTOK * DM / 4) / 256, 256>>>(x);

    dim3 wg(DM * DH / 4 / 256, NEXP, 3);     // 4096 x 8 x 3
    wcvt_kernel<<<wg, 256>>>(w1, w2, w3);

    dim3 g1(DH / 64, CAP / BM, NEXP);    // 32 x 20 x 8
    hmma_gemm_kernel<1><<<g1, 256, SMEM>>>();

    dim3 g2(DM / 128, CAP / BM, NEXP);   // 16 x 20 x 8
    hmma_gemm_kernel<2><<<g2, 256, SMEM>>>();

    int wc = (out_size >= NTOK * DM + NEXP) ? 1 : 0;
    combine_kernel<<<(NTOK * (DM / 8)) / 256, 256>>>(ew, out, wc);
}

// round 16
// speedup vs baseline: 1.3539x; 1.0429x over previous
#include <cuda_runtime.h>
#include <cuda_fp16.h>
#include <cstdint>

#define NTOK     8192
#define DM       2048
#define DH       2048
#define NEXP     8
#define TOPK     2
#define TASSIGN  (NTOK * TOPK)
#define CAP      2560

#define BM 128
#define BK 32
#define KIT (2048 / BK)        // 64 k-slabs
#define NSTAGE 4
#define STAGE_BYTES 16384      // A 8KB + B 8KB

// prep grid layout
#define PB_ROUTE 8
#define PB_X     (NTOK * DM / 8 / 256)          // 8192
#define PB_W     (DM * DH / 8 / 256)            // 16384 per weight-expert set? (full tensor: NEXP*DM*DH)
#define PB_WALL  (NEXP * DM * DH / 8 / 256)     // 16384 blocks per weight tensor

// ---------------- scratch (device globals) ----------------
__device__ int    g_counts[NEXP];
__device__ int    g_tok[NEXP * CAP];
__device__ int    g_slot[TASSIGN];
__device__ __half g_x16[(size_t)NTOK * DM];
__device__ __half g_w1f[(size_t)NEXP * DM * DH];   // fp16, ORIGINAL [d][h] layout
__device__ __half g_w2f[(size_t)NEXP * DH * DM];   // fp16, ORIGINAL [h][d] layout
__device__ __half g_w3f[(size_t)NEXP * DM * DH];
__device__ __half g_h  [(size_t)NEXP * CAP * DH];
__device__ float  g_y  [(size_t)NEXP * CAP * DM];

// ---------------- helpers ----------------
__device__ __forceinline__ uint32_t smem_u32(const void* p) {
    uint32_t a;
    asm("{ .reg .u64 t; cvta.to.shared.u64 t, %1; cvt.u32.u64 %0, t; }" : "=r"(a) : "l"(p));
    return a;
}
__device__ __forceinline__ uint32_t swz64(uint32_t o) { return o ^ ((o >> 3) & 0x30); }

__device__ __forceinline__ void cpasync16(uint32_t dst, const void* src) {
    asm volatile("cp.async.cg.shared.global [%0], [%1], 16;" :: "r"(dst), "l"(src) : "memory");
}
__device__ __forceinline__ void cp_commit() {
    asm volatile("cp.async.commit_group;" ::: "memory");
}
__device__ __forceinline__ void cp_wait2() {
    asm volatile("cp.async.wait_group 2;" ::: "memory");
}

__device__ __forceinline__ void ldsm4(uint32_t& r0, uint32_t& r1, uint32_t& r2, uint32_t& r3,
                                      uint32_t addr) {
    asm volatile("ldmatrix.sync.aligned.m8n8.x4.shared.b16 {%0,%1,%2,%3}, [%4];"
                 : "=r"(r0), "=r"(r1), "=r"(r2), "=r"(r3) : "r"(addr));
}
__device__ __forceinline__ void ldsm4t(uint32_t& r0, uint32_t& r1, uint32_t& r2, uint32_t& r3,
                                       uint32_t addr) {
    asm volatile("ldmatrix.sync.aligned.m8n8.x4.trans.shared.b16 {%0,%1,%2,%3}, [%4];"
                 : "=r"(r0), "=r"(r1), "=r"(r2), "=r"(r3) : "r"(addr));
}

__device__ __forceinline__ void mma16816(float* d, const uint32_t* a, const uint32_t* b) {
    asm volatile(
        "mma.sync.aligned.m16n8k16.row.col.f32.f16.f16.f32 "
        "{%0,%1,%2,%3}, {%4,%5,%6,%7}, {%8,%9}, {%0,%1,%2,%3};"
        : "+f"(d[0]), "+f"(d[1]), "+f"(d[2]), "+f"(d[3])
        : "r"(a[0]), "r"(a[1]), "r"(a[2]), "r"(a[3]), "r"(b[0]), "r"(b[1]));
}

__device__ __forceinline__ void cvt8(const float* __restrict__ src, __half* __restrict__ dst) {
    float4 v0 = *(const float4*)(src);
    float4 v1 = *(const float4*)(src + 4);
    __half2 h0 = __floats2half2_rn(v0.x, v0.y);
    __half2 h1 = __floats2half2_rn(v0.z, v0.w);
    __half2 h2 = __floats2half2_rn(v1.x, v1.y);
    __half2 h3 = __floats2half2_rn(v1.z, v1.w);
    uint4 pk;
    pk.x = *(uint32_t*)&h0;  pk.y = *(uint32_t*)&h1;
    pk.z = *(uint32_t*)&h2;  pk.w = *(uint32_t*)&h3;
    *(uint4*)dst = pk;
}

// ---------------- fused prep: route (blocks 0..7) + x/w converts ----------------
__global__ void prep_kernel(const int* __restrict__ idx, const float* __restrict__ x,
                            const float* __restrict__ w1, const float* __restrict__ w2,
                            const float* __restrict__ w3) {
    int b = blockIdx.x;
    const int tid = threadIdx.x;

    if (b < PB_ROUTE) {
        // ---- routing: 1 block per expert, stable cross-warp scan ----
        const int e    = b;
        const int wid  = tid >> 5;
        const int lane = tid & 31;
        __shared__ int wcnt[8];
        int base = 0;
        for (int t0 = 0; t0 < TASSIGN; t0 += 256) {
            int t = t0 + tid;
            bool m = (idx[t] == e);
            unsigned mask = __ballot_sync(0xffffffffu, m);
            if (lane == 0) wcnt[wid] = __popc(mask);
            __syncthreads();
            int pre = 0, tot = 0;
#pragma unroll
            for (int w = 0; w < 8; w++) {
                int c = wcnt[w];
                if (w < wid) pre += c;
                tot += c;
            }
            if (m) {
                int rank = base + pre + __popc(mask & ((1u << lane) - 1u));
                int slot = -1;
                if (rank < CAP) {
                    slot = e * CAP + rank;
                    g_tok[slot] = t / TOPK;
                }
                g_slot[t] = slot;
            }
            base += tot;
            __syncthreads();
        }
        if (tid == 0) g_counts[e] = base;
        return;
    }
    b -= PB_ROUTE;

    if (b < PB_X) {
        size_t i = ((size_t)b * 256 + tid) * 8;
        cvt8(x + i, g_x16 + i);
        return;
    }
    b -= PB_X;

    int T = b / PB_WALL;
    int r = b % PB_WALL;
    const float* w = (T == 0) ? w1 : (T == 1) ? w2 : w3;
    __half* dst    = (T == 0) ? g_w1f : (T == 1) ? g_w2f : g_w3f;
    size_t i = ((size_t)r * 256 + tid) * 8;
    cvt8(w + i, dst + i);
}

// ---------------- HMMA GEMM (fp16, BK=32, B via ldmatrix.trans) ----------------
// Stage: [A 8KB: 128 m-rows x 64B SW64][B 8KB: 32 k-rows x 256B, row-xor swizzle].
// MODE 1: fused x@w1 / x@w3 + SwiGLU -> g_h; B row = [w1 64h | w3 64h].
// MODE 2: h@w2 -> g_y; B row = 128 n-halves of w2.
template <int MODE>
__global__ __launch_bounds__(256, 2) void hmma_gemm_kernel() {
    const int e = blockIdx.z;
    int cnt = g_counts[e];
    if (cnt > CAP) cnt = CAP;
    const int m0 = blockIdx.y * BM;
    if (m0 >= cnt) return;
    const int n0 = blockIdx.x * ((MODE == 1) ? 64 : 128);

    extern __shared__ __align__(1024) char smem[];
    uint32_t sb = smem_u32(smem);

    const int tid  = threadIdx.x;
    const int lane = tid & 31;
    const int wid  = tid >> 5;

    // ---- A cp.async: rows rA0 (0..63) and rA1 (64..127), 16B chunk (tid&3) ----
    const int rA0 = tid >> 2;
    const int rA1 = rA0 + 64;
    const int cA  = (tid & 3) * 8;      // halves
    const __half* paj[2];
    if (MODE == 1) {
        paj[0] = g_x16 + (size_t)g_tok[e * CAP + m0 + rA0] * DM + cA;
        paj[1] = g_x16 + (size_t)g_tok[e * CAP + m0 + rA1] * DM + cA;
    } else {
        paj[0] = g_h + ((size_t)e * CAP + m0 + rA0) * DH + cA;
        paj[1] = g_h + ((size_t)e * CAP + m0 + rA1) * DH + cA;
    }
    uint32_t soA[2];
    soA[0] = sb + swz64((uint32_t)(rA0 * 64 + (tid & 3) * 16));
    soA[1] = sb + swz64((uint32_t)(rA1 * 64 + (tid & 3) * 16));

    // ---- B cp.async: K-major rows. thread t -> k-rows (t>>4) and (t>>4)+16, n-chunk t&15 ----
    const int rB0 = tid >> 4;           // 0..15
    const int rB1 = rB0 + 16;           // 16..31
    const int cB  = tid & 15;           // 16B chunk within 256B row
    const __half* pbj[2];
    {
        int rBv[2] = {rB0, rB1};
#pragma unroll
        for (int j = 0; j < 2; j++) {
            int rb = rBv[j];
            if (MODE == 1) {
                if (cB < 8)
                    pbj[j] = g_w1f + ((size_t)e * DM + rb) * DH + n0 + cB * 8;
                else
                    pbj[j] = g_w3f + ((size_t)e * DM + rb) * DH + n0 + (cB - 8) * 8;
            } else {
                pbj[j] = g_w2f + ((size_t)e * DH + rb) * DM + n0 + cB * 8;
            }
        }
    }
    const uint32_t swB = (uint32_t)((rB0 & 7) << 4);
    uint32_t soB[2];
    soB[0] = sb + 8192 + (((uint32_t)(rB0 * 256 + cB * 16)) ^ swB);
    soB[1] = sb + 8192 + (((uint32_t)(rB1 * 256 + cB * 16)) ^ swB);
    const size_t bstep = (size_t)BK * ((MODE == 1) ? DH : DM);

    // ---- warp tiling ----
    int wm, wn, mat;
    if (MODE == 1) { wm = wid & 1; wn = (wid >> 1) & 1; mat = wid >> 2; }
    else           { wm = wid & 1; wn = wid >> 1;       mat = 0; }
    const int mbase = wm * 64;
    const int nbB   = (MODE == 1) ? (mat * 64 + wn * 32) : (wn * 32);

    const int lrow = lane & 15;
    const int lkb  = (lane & 16) ? 16 : 0;

    uint32_t baseA[4], baseAx[4];
#pragma unroll
    for (int mi = 0; mi < 4; mi++) {
        uint32_t pre = (uint32_t)((mbase + mi * 16 + lrow) * 64 + lkb);
        baseA[mi]  = sb + swz64(pre);
        baseAx[mi] = sb + swz64(pre ^ 32u);
    }
    const int gB = lane >> 3;
    const int lr = lane & 7;
    uint32_t baseBT[2];
#pragma unroll
    for (int j = 0; j < 2; j++) {
        uint32_t o = (uint32_t)((((gB & 1) * 8 + lr) * 256) +
                                (nbB + j * 16 + (gB >> 1) * 8) * 2);
        baseBT[j] = sb + 8192 + (o ^ ((uint32_t)lr << 4));
    }

    float acc[4][4][4];
#pragma unroll
    for (int mi = 0; mi < 4; mi++)
#pragma unroll
        for (int ni = 0; ni < 4; ni++)
#pragma unroll
            for (int q = 0; q < 4; q++) acc[mi][ni][q] = 0.f;

    // ---- prologue: slabs 0..NSTAGE-2 ----
#pragma unroll
    for (int s = 0; s < NSTAGE - 1; s++) {
        uint32_t o = s * STAGE_BYTES;
        cpasync16(soA[0] + o, paj[0] + s * BK);
        cpasync16(soA[1] + o, paj[1] + s * BK);
        cpasync16(soB[0] + o, pbj[0] + s * bstep);
        cpasync16(soB[1] + o, pbj[1] + s * bstep);
        cp_commit();
    }
    paj[0] += (NSTAGE - 1) * BK;    paj[1] += (NSTAGE - 1) * BK;
    pbj[0] += (NSTAGE - 1) * bstep; pbj[1] += (NSTAGE - 1) * bstep;

    int kt = 0;
#pragma unroll 1
    for (int blk = 0; blk < KIT / NSTAGE; blk++) {
#pragma unroll
        for (int s = 0; s < NSTAGE; s++) {
            cp_wait2();
            __syncthreads();

            if (kt + NSTAGE - 1 < KIT) {
                const uint32_t wo = ((s + NSTAGE - 1) & (NSTAGE - 1)) * STAGE_BYTES;
                cpasync16(soA[0] + wo, paj[0]);
                cpasync16(soA[1] + wo, paj[1]);
                cpasync16(soB[0] + wo, pbj[0]);
                cpasync16(soB[1] + wo, pbj[1]);
            }
            cp_commit();
            paj[0] += BK;    paj[1] += BK;
            pbj[0] += bstep; pbj[1] += bstep;

            const uint32_t so = s * STAGE_BYTES;

            uint32_t bf[2][4][2];
#pragma unroll
            for (int c = 0; c < 2; c++) {
#pragma unroll
                for (int j = 0; j < 2; j++) {
                    uint32_t q0, q1, q2, q3;
                    ldsm4t(q0, q1, q2, q3, baseBT[j] + so + (uint32_t)(c * 4096));
                    bf[c][j * 2 + 0][0] = q0; bf[c][j * 2 + 0][1] = q1;
                    bf[c][j * 2 + 1][0] = q2; bf[c][j * 2 + 1][1] = q3;
                }
            }

#pragma unroll
            for (int c = 0; c < 2; c++) {
                uint32_t af[4][4];
#pragma unroll
                for (int mi = 0; mi < 4; mi++)
                    ldsm4(af[mi][0], af[mi][1], af[mi][2], af[mi][3],
                          (c ? baseAx[mi] : baseA[mi]) + so);
#pragma unroll
                for (int mi = 0; mi < 4; mi++)
#pragma unroll
                    for (int ni = 0; ni < 4; ni++)
                        mma16816(acc[mi][ni], af[mi], bf[c][ni]);
            }
            kt++;
        }
    }

    // ---- epilogue ----
    __syncthreads();
    if (MODE == 1) {
        float* fb = (float*)smem;
        if (mat == 1) {
#pragma unroll
            for (int mi = 0; mi < 4; mi++)
#pragma unroll
                for (int ni = 0; ni < 4; ni++) {
                    int ml = mbase + mi * 16 + (lane >> 2);
                    int nl = wn * 32 + ni * 8 + 2 * (lane & 3);
                    fb[ml * 64 + nl]           = acc[mi][ni][0];
                    fb[ml * 64 + nl + 1]       = acc[mi][ni][1];
                    fb[(ml + 8) * 64 + nl]     = acc[mi][ni][2];
                    fb[(ml + 8) * 64 + nl + 1] = acc[mi][ni][3];
                }
        }
        __syncthreads();
        if (mat == 0) {
#pragma unroll
            for (int mi = 0; mi < 4; mi++)
#pragma unroll
                for (int ni = 0; ni < 4; ni++) {
                    int ml = mbase + mi * 16 + (lane >> 2);
                    int nl = wn * 32 + ni * 8 + 2 * (lane & 3);
#pragma unroll
                    for (int hrow = 0; hrow < 2; hrow++) {
                        int mloc = ml + hrow * 8;
                        int row  = m0 + mloc;
                        if (row >= cnt) continue;
                        float a10 = acc[mi][ni][2 * hrow + 0];
                        float a11 = acc[mi][ni][2 * hrow + 1];
                        float a30 = fb[mloc * 64 + nl];
                        float a31 = fb[mloc * 64 + nl + 1];
                        float h0 = (a10 / (1.f + __expf(-a10))) * a30;
                        float h1 = (a11 / (1.f + __expf(-a11))) * a31;
                        __half2 hp = __floats2half2_rn(h0, h1);
                        size_t o = ((size_t)e * CAP + row) * DH + n0 + nl;
                        *(__half2*)(g_h + o) = hp;
                    }
                }
        }
    } else {
#pragma unroll
        for (int mi = 0; mi < 4; mi++)
#pragma unroll
            for (int ni = 0; ni < 4; ni++) {
                int ml = mbase + mi * 16 + (lane >> 2);
                int nl = nbB + ni * 8 + 2 * (lane & 3);
#pragma unroll
                for (int hrow = 0; hrow < 2; hrow++) {
                    int row = m0 + ml + hrow * 8;
                    if (row >= cnt) continue;
                    float2 v = make_float2(acc[mi][ni][2 * hrow], acc[mi][ni][2 * hrow + 1]);
                    *(float2*)(g_y + ((size_t)e * CAP + row) * DM + n0 + nl) = v;
                }
            }
    }
}

// ---------------- combine (+ counts tail fused), 16 floats/thread ----------------
__global__ void combine_kernel(const float* __restrict__ ew, float* __restrict__ out,
                               int write_counts) {
    int i = blockIdx.x * blockDim.x + threadIdx.x;
    int n = i / (DM / 16);
    int c = (i % (DM / 16)) * 16;
    float4 r[4];
#pragma unroll
    for (int q = 0; q < 4; q++) r[q] = make_float4(0.f, 0.f, 0.f, 0.f);
#pragma unroll
    for (int k = 0; k < TOPK; k++) {
        int slot = g_slot[n * TOPK + k];
        if (slot >= 0) {
            float w = ew[n * TOPK + k];
            const float* yp = g_y + (size_t)slot * DM + c;
#pragma unroll
            for (int q = 0; q < 4; q++) {
                float4 v = *(const float4*)(yp + 4 * q);
                r[q].x = fmaf(w, v.x, r[q].x);
                r[q].y = fmaf(w, v.y, r[q].y);
                r[q].z = fmaf(w, v.z, r[q].z);
                r[q].w = fmaf(w, v.w, r[q].w);
            }
        }
    }
    float* op = out + (size_t)n * DM + c;
#pragma unroll
    for (int q = 0; q < 4; q++) *(float4*)(op + 4 * q) = r[q];

    if (write_counts && blockIdx.x == 0 && threadIdx.x < NEXP)
        out[(size_t)NTOK * DM + threadIdx.x] = (float)g_counts[threadIdx.x];
}

// ---------------- launch ----------------
extern "C" void kernel_launch(void* const* d_in, const int* in_sizes, int n_in,
                              void* d_out, int out_size) {
    const float* x  = (const float*)d_in[0];
    const float* ew = (const float*)d_in[1];
    const int*   ix = (const int*)  d_in[2];
    const float* w1 = (const float*)d_in[3];
    const float* w2 = (const float*)d_in[4];
    const float* w3 = (const float*)d_in[5];
    float* out = (float*)d_out;

    const int SMEM = NSTAGE * STAGE_BYTES;   // 65536
    cudaFuncSetAttribute(hmma_gemm_kernel<1>, cudaFuncAttributeMaxDynamicSharedMemorySize, SMEM);
    cudaFuncSetAttribute(hmma_gemm_kernel<2>, cudaFuncAttributeMaxDynamicSharedMemorySize, SMEM);

    int prep_blocks = PB_ROUTE + PB_X + 3 * PB_WALL;
    prep_kernel<<<prep_blocks, 256>>>(ix, x, w1, w2, w3);

    dim3 g1(DH / 64, CAP / BM, NEXP);    // 32 x 20 x 8
    hmma_gemm_kernel<1><<<g1, 256, SMEM>>>();

    dim3 g2(DM / 128, CAP / BM, NEXP);   // 16 x 20 x 8
    hmma_gemm_kernel<2><<<g2, 256, SMEM>>>();

    int wc = (out_size >= NTOK * DM + NEXP) ? 1 : 0;
    combine_kernel<<<(NTOK * (DM / 16)) / 256, 256>>>(ew, out, wc);
}

// round 17
// speedup vs baseline: 1.3586x; 1.0034x over previous
#include <cuda_runtime.h>
#include <cuda_fp16.h>
#include <cstdint>

#define NTOK     8192
#define DM       2048
#define DH       2048
#define NEXP     8
#define TOPK     2
#define TASSIGN  (NTOK * TOPK)
#define CAP      2560

#define BM 128
#define BK 32
#define KIT (2048 / BK)        // 64 k-slabs
#define NSTAGE 4
#define STAGE_BYTES 16384      // A 8KB + B 8KB

// prep grid layout
#define PB_ROUTE 8
#define PB_X     (NTOK * DM / 8 / 256)          // 8192
#define PB_WALL  (NEXP * DM * DH / 8 / 256)     // 16384 blocks per weight tensor

// ---------------- scratch (device globals) ----------------
__device__ int    g_counts[NEXP];
__device__ int    g_tok[NEXP * CAP];
__device__ int    g_slot[TASSIGN];
__device__ __half g_x16[(size_t)NTOK * DM];
__device__ __half g_w1f[(size_t)NEXP * DM * DH];   // fp16, ORIGINAL [d][h] layout
__device__ __half g_w2f[(size_t)NEXP * DH * DM];   // fp16, ORIGINAL [h][d] layout
__device__ __half g_w3f[(size_t)NEXP * DM * DH];
__device__ __half g_h  [(size_t)NEXP * CAP * DH];
__device__ __half g_y  [(size_t)NEXP * CAP * DM];  // fp16 (was fp32)

// ---------------- helpers ----------------
__device__ __forceinline__ uint32_t smem_u32(const void* p) {
    uint32_t a;
    asm("{ .reg .u64 t; cvta.to.shared.u64 t, %1; cvt.u32.u64 %0, t; }" : "=r"(a) : "l"(p));
    return a;
}
__device__ __forceinline__ uint32_t swz64(uint32_t o) { return o ^ ((o >> 3) & 0x30); }

__device__ __forceinline__ void cpasync16(uint32_t dst, const void* src) {
    asm volatile("cp.async.cg.shared.global [%0], [%1], 16;" :: "r"(dst), "l"(src) : "memory");
}
__device__ __forceinline__ void cp_commit() {
    asm volatile("cp.async.commit_group;" ::: "memory");
}
__device__ __forceinline__ void cp_wait2() {
    asm volatile("cp.async.wait_group 2;" ::: "memory");
}

__device__ __forceinline__ void ldsm4(uint32_t& r0, uint32_t& r1, uint32_t& r2, uint32_t& r3,
                                      uint32_t addr) {
    asm volatile("ldmatrix.sync.aligned.m8n8.x4.shared.b16 {%0,%1,%2,%3}, [%4];"
                 : "=r"(r0), "=r"(r1), "=r"(r2), "=r"(r3) : "r"(addr));
}
__device__ __forceinline__ void ldsm4t(uint32_t& r0, uint32_t& r1, uint32_t& r2, uint32_t& r3,
                                       uint32_t addr) {
    asm volatile("ldmatrix.sync.aligned.m8n8.x4.trans.shared.b16 {%0,%1,%2,%3}, [%4];"
                 : "=r"(r0), "=r"(r1), "=r"(r2), "=r"(r3) : "r"(addr));
}

__device__ __forceinline__ void mma16816(float* d, const uint32_t* a, const uint32_t* b) {
    asm volatile(
        "mma.sync.aligned.m16n8k16.row.col.f32.f16.f16.f32 "
        "{%0,%1,%2,%3}, {%4,%5,%6,%7}, {%8,%9}, {%0,%1,%2,%3};"
        : "+f"(d[0]), "+f"(d[1]), "+f"(d[2]), "+f"(d[3])
        : "r"(a[0]), "r"(a[1]), "r"(a[2]), "r"(a[3]), "r"(b[0]), "r"(b[1]));
}

__device__ __forceinline__ void cvt8(const float* __restrict__ src, __half* __restrict__ dst) {
    float4 v0 = *(const float4*)(src);
    float4 v1 = *(const float4*)(src + 4);
    __half2 h0 = __floats2half2_rn(v0.x, v0.y);
    __half2 h1 = __floats2half2_rn(v0.z, v0.w);
    __half2 h2 = __floats2half2_rn(v1.x, v1.y);
    __half2 h3 = __floats2half2_rn(v1.z, v1.w);
    uint4 pk;
    pk.x = *(uint32_t*)&h0;  pk.y = *(uint32_t*)&h1;
    pk.z = *(uint32_t*)&h2;  pk.w = *(uint32_t*)&h3;
    *(uint4*)dst = pk;
}

// ---------------- fused prep: route (blocks 0..7) + x/w converts ----------------
__global__ void prep_kernel(const int* __restrict__ idx, const float* __restrict__ x,
                            const float* __restrict__ w1, const float* __restrict__ w2,
                            const float* __restrict__ w3) {
    int b = blockIdx.x;
    const int tid = threadIdx.x;

    if (b < PB_ROUTE) {
        const int e    = b;
        const int wid  = tid >> 5;
        const int lane = tid & 31;
        __shared__ int wcnt[8];
        int base = 0;
        for (int t0 = 0; t0 < TASSIGN; t0 += 256) {
            int t = t0 + tid;
            bool m = (idx[t] == e);
            unsigned mask = __ballot_sync(0xffffffffu, m);
            if (lane == 0) wcnt[wid] = __popc(mask);
            __syncthreads();
            int pre = 0, tot = 0;
#pragma unroll
            for (int w = 0; w < 8; w++) {
                int c = wcnt[w];
                if (w < wid) pre += c;
                tot += c;
            }
            if (m) {
                int rank = base + pre + __popc(mask & ((1u << lane) - 1u));
                int slot = -1;
                if (rank < CAP) {
                    slot = e * CAP + rank;
                    g_tok[slot] = t / TOPK;
                }
                g_slot[t] = slot;
            }
            base += tot;
            __syncthreads();
        }
        if (tid == 0) g_counts[e] = base;
        return;
    }
    b -= PB_ROUTE;

    if (b < PB_X) {
        size_t i = ((size_t)b * 256 + tid) * 8;
        cvt8(x + i, g_x16 + i);
        return;
    }
    b -= PB_X;

    int T = b / PB_WALL;
    int r = b % PB_WALL;
    const float* w = (T == 0) ? w1 : (T == 1) ? w2 : w3;
    __half* dst    = (T == 0) ? g_w1f : (T == 1) ? g_w2f : g_w3f;
    size_t i = ((size_t)r * 256 + tid) * 8;
    cvt8(w + i, dst + i);
}

// ---------------- HMMA GEMM (fp16, BK=32, B via ldmatrix.trans) ----------------
// Stage: [A 8KB: 128 m-rows x 64B SW64][B 8KB: 32 k-rows x 256B, row-xor swizzle].
// MODE 1: fused x@w1 / x@w3 + SwiGLU -> g_h; B row = [w1 64h | w3 64h].
// MODE 2: h@w2 -> g_y (fp16); B row = 128 n-halves of w2.
template <int MODE>
__global__ __launch_bounds__(256, 2) void hmma_gemm_kernel() {
    const int e = blockIdx.z;
    int cnt = g_counts[e];
    if (cnt > CAP) cnt = CAP;
    const int m0 = blockIdx.y * BM;
    if (m0 >= cnt) return;
    const int n0 = blockIdx.x * ((MODE == 1) ? 64 : 128);

    extern __shared__ __align__(1024) char smem[];
    uint32_t sb = smem_u32(smem);

    const int tid  = threadIdx.x;
    const int lane = tid & 31;
    const int wid  = tid >> 5;

    // ---- A cp.async: rows rA0 (0..63) and rA1 (64..127), 16B chunk (tid&3) ----
    const int rA0 = tid >> 2;
    const int rA1 = rA0 + 64;
    const int cA  = (tid & 3) * 8;      // halves
    const __half* paj[2];
    if (MODE == 1) {
        paj[0] = g_x16 + (size_t)g_tok[e * CAP + m0 + rA0] * DM + cA;
        paj[1] = g_x16 + (size_t)g_tok[e * CAP + m0 + rA1] * DM + cA;
    } else {
        paj[0] = g_h + ((size_t)e * CAP + m0 + rA0) * DH + cA;
        paj[1] = g_h + ((size_t)e * CAP + m0 + rA1) * DH + cA;
    }
    uint32_t soA[2];
    soA[0] = sb + swz64((uint32_t)(rA0 * 64 + (tid & 3) * 16));
    soA[1] = sb + swz64((uint32_t)(rA1 * 64 + (tid & 3) * 16));

    // ---- B cp.async: K-major rows. thread t -> k-rows (t>>4) and (t>>4)+16, n-chunk t&15 ----
    const int rB0 = tid >> 4;
    const int rB1 = rB0 + 16;
    const int cB  = tid & 15;
    const __half* pbj[2];
    {
        int rBv[2] = {rB0, rB1};
#pragma unroll
        for (int j = 0; j < 2; j++) {
            int rb = rBv[j];
            if (MODE == 1) {
                if (cB < 8)
                    pbj[j] = g_w1f + ((size_t)e * DM + rb) * DH + n0 + cB * 8;
                else
                    pbj[j] = g_w3f + ((size_t)e * DM + rb) * DH + n0 + (cB - 8) * 8;
            } else {
                pbj[j] = g_w2f + ((size_t)e * DH + rb) * DM + n0 + cB * 8;
            }
        }
    }
    const uint32_t swB = (uint32_t)((rB0 & 7) << 4);
    uint32_t soB[2];
    soB[0] = sb + 8192 + (((uint32_t)(rB0 * 256 + cB * 16)) ^ swB);
    soB[1] = sb + 8192 + (((uint32_t)(rB1 * 256 + cB * 16)) ^ swB);
    const size_t bstep = (size_t)BK * ((MODE == 1) ? DH : DM);

    // ---- warp tiling ----
    int wm, wn, mat;
    if (MODE == 1) { wm = wid & 1; wn = (wid >> 1) & 1; mat = wid >> 2; }
    else           { wm = wid & 1; wn = wid >> 1;       mat = 0; }
    const int mbase = wm * 64;
    const int nbB   = (MODE == 1) ? (mat * 64 + wn * 32) : (wn * 32);

    const int lrow = lane & 15;
    const int lkb  = (lane & 16) ? 16 : 0;

    uint32_t baseA[4], baseAx[4];
#pragma unroll
    for (int mi = 0; mi < 4; mi++) {
        uint32_t pre = (uint32_t)((mbase + mi * 16 + lrow) * 64 + lkb);
        baseA[mi]  = sb + swz64(pre);
        baseAx[mi] = sb + swz64(pre ^ 32u);
    }
    const int gB = lane >> 3;
    const int lr = lane & 7;
    uint32_t baseBT[2];
#pragma unroll
    for (int j = 0; j < 2; j++) {
        uint32_t o = (uint32_t)((((gB & 1) * 8 + lr) * 256) +
                                (nbB + j * 16 + (gB >> 1) * 8) * 2);
        baseBT[j] = sb + 8192 + (o ^ ((uint32_t)lr << 4));
    }

    float acc[4][4][4];
#pragma unroll
    for (int mi = 0; mi < 4; mi++)
#pragma unroll
        for (int ni = 0; ni < 4; ni++)
#pragma unroll
            for (int q = 0; q < 4; q++) acc[mi][ni][q] = 0.f;

    // ---- prologue: slabs 0..NSTAGE-2 ----
#pragma unroll
    for (int s = 0; s < NSTAGE - 1; s++) {
        uint32_t o = s * STAGE_BYTES;
        cpasync16(soA[0] + o, paj[0] + s * BK);
        cpasync16(soA[1] + o, paj[1] + s * BK);
        cpasync16(soB[0] + o, pbj[0] + s * bstep);
        cpasync16(soB[1] + o, pbj[1] + s * bstep);
        cp_commit();
    }
    paj[0] += (NSTAGE - 1) * BK;    paj[1] += (NSTAGE - 1) * BK;
    pbj[0] += (NSTAGE - 1) * bstep; pbj[1] += (NSTAGE - 1) * bstep;

    int kt = 0;
#pragma unroll 1
    for (int blk = 0; blk < KIT / NSTAGE; blk++) {
#pragma unroll
        for (int s = 0; s < NSTAGE; s++) {
            cp_wait2();
            __syncthreads();

            if (kt + NSTAGE - 1 < KIT) {
                const uint32_t wo = ((s + NSTAGE - 1) & (NSTAGE - 1)) * STAGE_BYTES;
                cpasync16(soA[0] + wo, paj[0]);
                cpasync16(soA[1] + wo, paj[1]);
                cpasync16(soB[0] + wo, pbj[0]);
                cpasync16(soB[1] + wo, pbj[1]);
            }
            cp_commit();
            paj[0] += BK;    paj[1] += BK;
            pbj[0] += bstep; pbj[1] += bstep;

            const uint32_t so = s * STAGE_BYTES;

            uint32_t bf[2][4][2];
#pragma unroll
            for (int c = 0; c < 2; c++) {
#pragma unroll
                for (int j = 0; j < 2; j++) {
                    uint32_t q0, q1, q2, q3;
                    ldsm4t(q0, q1, q2, q3, baseBT[j] + so + (uint32_t)(c * 4096));
                    bf[c][j * 2 + 0][0] = q0; bf[c][j * 2 + 0][1] = q1;
                    bf[c][j * 2 + 1][0] = q2; bf[c][j * 2 + 1][1] = q3;
                }
            }

#pragma unroll
            for (int c = 0; c < 2; c++) {
                uint32_t af[4][4];
#pragma unroll
                for (int mi = 0; mi < 4; mi++)
                    ldsm4(af[mi][0], af[mi][1], af[mi][2], af[mi][3],
                          (c ? baseAx[mi] : baseA[mi]) + so);
#pragma unroll
                for (int mi = 0; mi < 4; mi++)
#pragma unroll
                    for (int ni = 0; ni < 4; ni++)
                        mma16816(acc[mi][ni], af[mi], bf[c][ni]);
            }
            kt++;
        }
    }

    // ---- epilogue ----
    __syncthreads();
    if (MODE == 1) {
        float* fb = (float*)smem;
        if (mat == 1) {
#pragma unroll
            for (int mi = 0; mi < 4; mi++)
#pragma unroll
                for (int ni = 0; ni < 4; ni++) {
                    int ml = mbase + mi * 16 + (lane >> 2);
                    int nl = wn * 32 + ni * 8 + 2 * (lane & 3);
                    fb[ml * 64 + nl]           = acc[mi][ni][0];
                    fb[ml * 64 + nl + 1]       = acc[mi][ni][1];
                    fb[(ml + 8) * 64 + nl]     = acc[mi][ni][2];
                    fb[(ml + 8) * 64 + nl + 1] = acc[mi][ni][3];
                }
        }
        __syncthreads();
        if (mat == 0) {
#pragma unroll
            for (int mi = 0; mi < 4; mi++)
#pragma unroll
                for (int ni = 0; ni < 4; ni++) {
                    int ml = mbase + mi * 16 + (lane >> 2);
                    int nl = wn * 32 + ni * 8 + 2 * (lane & 3);
#pragma unroll
                    for (int hrow = 0; hrow < 2; hrow++) {
                        int mloc = ml + hrow * 8;
                        int row  = m0 + mloc;
                        if (row >= cnt) continue;
                        float a10 = acc[mi][ni][2 * hrow + 0];
                        float a11 = acc[mi][ni][2 * hrow + 1];
                        float a30 = fb[mloc * 64 + nl];
                        float a31 = fb[mloc * 64 + nl + 1];
                        float h0 = (a10 / (1.f + __expf(-a10))) * a30;
                        float h1 = (a11 / (1.f + __expf(-a11))) * a31;
                        __half2 hp = __floats2half2_rn(h0, h1);
                        size_t o = ((size_t)e * CAP + row) * DH + n0 + nl;
                        *(__half2*)(g_h + o) = hp;
                    }
                }
        }
    } else {
#pragma unroll
        for (int mi = 0; mi < 4; mi++)
#pragma unroll
            for (int ni = 0; ni < 4; ni++) {
                int ml = mbase + mi * 16 + (lane >> 2);
                int nl = nbB + ni * 8 + 2 * (lane & 3);
#pragma unroll
                for (int hrow = 0; hrow < 2; hrow++) {
                    int row = m0 + ml + hrow * 8;
                    if (row >= cnt) continue;
                    __half2 hp = __floats2half2_rn(acc[mi][ni][2 * hrow],
                                                   acc[mi][ni][2 * hrow + 1]);
                    *(__half2*)(g_y + ((size_t)e * CAP + row) * DM + n0 + nl) = hp;
                }
            }
    }
}

// ---------------- combine (+ counts tail fused), 16 halves/thread ----------------
__global__ void combine_kernel(const float* __restrict__ ew, float* __restrict__ out,
                               int write_counts) {
    int i = blockIdx.x * blockDim.x + threadIdx.x;
    int n = i / (DM / 16);
    int c = (i % (DM / 16)) * 16;
    float r[16];
#pragma unroll
    for (int q = 0; q < 16; q++) r[q] = 0.f;
#pragma unroll
    for (int k = 0; k < TOPK; k++) {
        int slot = g_slot[n * TOPK + k];
        if (slot >= 0) {
            float w = ew[n * TOPK + k];
            const __half* yp = g_y + (size_t)slot * DM + c;
            uint4 raw0 = *(const uint4*)(yp);
            uint4 raw1 = *(const uint4*)(yp + 8);
            const uint32_t* rw = &raw0.x;
#pragma unroll
            for (int q = 0; q < 4; q++) {
                float2 v = __half22float2(*(const __half2*)&rw[q]);
                r[2 * q]     = fmaf(w, v.x, r[2 * q]);
                r[2 * q + 1] = fmaf(w, v.y, r[2 * q + 1]);
            }
            const uint32_t* rw1 = &raw1.x;
#pragma unroll
            for (int q = 0; q < 4; q++) {
                float2 v = __half22float2(*(const __half2*)&rw1[q]);
                r[8 + 2 * q]     = fmaf(w, v.x, r[8 + 2 * q]);
                r[8 + 2 * q + 1] = fmaf(w, v.y, r[8 + 2 * q + 1]);
            }
        }
    }
    float* op = out + (size_t)n * DM + c;
#pragma unroll
    for (int q = 0; q < 4; q++)
        *(float4*)(op + 4 * q) = make_float4(r[4 * q], r[4 * q + 1], r[4 * q + 2], r[4 * q + 3]);

    if (write_counts && blockIdx.x == 0 && threadIdx.x < NEXP)
        out[(size_t)NTOK * DM + threadIdx.x] = (float)g_counts[threadIdx.x];
}

// ---------------- launch ----------------
extern "C" void kernel_launch(void* const* d_in, const int* in_sizes, int n_in,
                              void* d_out, int out_size) {
    const float* x  = (const float*)d_in[0];
    const float* ew = (const float*)d_in[1];
    const int*   ix = (const int*)  d_in[2];
    const float* w1 = (const float*)d_in[3];
    const float* w2 = (const float*)d_in[4];
    const float* w3 = (const float*)d_in[5];
    float* out = (float*)d_out;

    const int SMEM = NSTAGE * STAGE_BYTES;   // 65536
    cudaFuncSetAttribute(hmma_gemm_kernel<1>, cudaFuncAttributeMaxDynamicSharedMemorySize, SMEM);
    cudaFuncSetAttribute(hmma_gemm_kernel<2>, cudaFuncAttributeMaxDynamicSharedMemorySize, SMEM);

    int prep_blocks = PB_ROUTE + PB_X + 3 * PB_WALL;
    prep_kernel<<<prep_blocks, 256>>>(ix, x, w1, w2, w3);

    dim3 g1(DH / 64, CAP / BM, NEXP);    // 32 x 20 x 8
    hmma_gemm_kernel<1><<<g1, 256, SMEM>>>();

    dim3 g2(DM / 128, CAP / BM, NEXP);   // 16 x 20 x 8
    hmma_gemm_kernel<2><<<g2, 256, SMEM>>>();

    int wc = (out_size >= NTOK * DM + NEXP) ? 1 : 0;
    combine_kernel<<<(NTOK * (DM / 16)) / 256, 256>>>(ew, out, wc);
}